// round 8
// baseline (speedup 1.0000x reference)
#include <cuda_runtime.h>
#include <cuda_fp16.h>

// HausdorffDTLoss, [4,1,256,256] fp32 inputs. Single fused kernel, all-fp32.
// loss = mean( (pred-target)^2 * (pred_dt^2 + target_dt^2) )
// dt^2 = min(F_fg,BIG) + min(F_~fg,BIG)  (exactly one EDT is 0 per pixel).
// F = separable 1D min-plus squared-distance transform (y-pass then x-pass),
// windowed outward scan with per-lane early exit (exact: candidates are
// f[j]+(i-j)^2, f>=0; d^2>=min can't win; clamped-index candidates are
// dominated by the already-evaluated d=|i-j| candidate).
//
// NO FP64 anywhere: B300 DFMA rt ~18.4 cyc/SM (~40x slower than FFMA) was
// the hidden cost in every previous round. fp32 tree reduction error
// (~1.5e-5 rel) is far within the 1e-3 threshold.

#define BIGF 1e10f
#define HW 256
#define IMG 65536
#define TOTAL 262144
#define ARR 257
#define NBLK 256

// [img(2)][b(4)][x][y] signed vertical-pass field (y fast; transposed)
__device__ __align__(16) __half g_V[2 * 4 * IMG];
// [b(4)][y][x] quantized squared error, e_q = round(e * 65535)
__device__ __align__(16) unsigned short g_E[4 * IMG];
__device__ int g_fgany[8];          // [img*4 + b]; zero-init, self-reset
__device__ float g_accum;           // zero-init, self-reset
__device__ unsigned int g_counter;  // zero-init, self-reset
__device__ volatile unsigned int g_bar;  // zero-init, self-reset

// Windowed min-plus over 4 signed arrays (stride ARR) concurrently.
// Signed decode: fg-field value = max(v,0), ~fg-field value = max(-v,0).
__device__ __forceinline__ void scan4s(const float* __restrict__ A, int i,
                                       float mF[4], float mN[4])
{
    #pragma unroll
    for (int j = 0; j < 4; ++j) {
        float f = A[i + j * ARR];
        mF[j] = fmaxf(f, 0.0f);
        mN[j] = fmaxf(-f, 0.0f);
    }
    float d2 = 1.0f, st = 3.0f;      // d2 = d*d, st = 2d+1 (exact in fp32)
    #pragma unroll 1
    for (int d = 1; d < 256; ++d) {
        float mx = fmaxf(fmaxf(fmaxf(mF[0], mN[0]), fmaxf(mF[1], mN[1])),
                         fmaxf(fmaxf(mF[2], mN[2]), fmaxf(mF[3], mN[3])));
        if (d2 >= mx) break;         // no farther candidate can win any min
        int il = i - d; il = il < 0 ? 0 : il;       // clamped: dominated
        int ir = i + d; ir = ir > 255 ? 255 : ir;
        #pragma unroll
        for (int j = 0; j < 4; ++j) {
            float vl = A[il + j * ARR];
            float vr = A[ir + j * ARR];
            mF[j] = fminf(mF[j], fminf(fmaxf(vl, 0.0f), fmaxf(vr, 0.0f)) + d2);
            mN[j] = fminf(mN[j], fminf(fmaxf(-vl, 0.0f), fmaxf(-vr, 0.0f)) + d2);
        }
        d2 += st; st += 2.0f;
    }
}

__global__ __launch_bounds__(512, 2) void fused_kernel(
    const float* __restrict__ pred, const float* __restrict__ target,
    float* __restrict__ out)
{
    __shared__ float s[8 * ARR];     // reused across both phases
    int bid = blockIdx.x;            // 0..255
    int tid = threadIdx.x;

    // ===================== Phase 1: vertical pass ========================
    {
        int xt  = bid & 63;
        int b   = bid >> 6;
        int x0  = xt * 4;
        int img = tid >> 8;          // 0 = pred, 1 = target (warp-uniform)
        int y   = tid & 255;

        const float* im = (img ? target : pred) + b * IMG + y * HW + x0;
        float4 v = *reinterpret_cast<const float4*>(im);   // coalesced 16B

        // Stash raw values: array a = col*2 + img
        s[(0 * 2 + img) * ARR + y] = v.x;
        s[(1 * 2 + img) * ARR + y] = v.y;
        s[(2 * 2 + img) * ARR + y] = v.z;
        s[(3 * 2 + img) * ARR + y] = v.w;

        bool fgl = (v.x > 0.5f) || (v.y > 0.5f) || (v.z > 0.5f) || (v.w > 0.5f);
        if (__any_sync(0xFFFFFFFFu, fgl) && (tid & 31) == 0)
            atomicOr(&g_fgany[img * 4 + b], 1);
        __syncthreads();

        // pred-threads compute e against stashed target values.
        if (img == 0) {
            float d0 = v.x - s[1 * ARR + y];
            float d1 = v.y - s[3 * ARR + y];
            float d2_ = v.z - s[5 * ARR + y];
            float d3 = v.w - s[7 * ARR + y];
            ushort4 eq;
            eq.x = (unsigned short)(d0 * d0 * 65535.0f + 0.5f);
            eq.y = (unsigned short)(d1 * d1 * 65535.0f + 0.5f);
            eq.z = (unsigned short)(d2_ * d2_ * 65535.0f + 0.5f);
            eq.w = (unsigned short)(d3 * d3 * 65535.0f + 0.5f);
            *reinterpret_cast<ushort4*>(g_E + b * IMG + y * HW + x0) = eq;
        }
        __syncthreads();             // raw values consumed

        // Convert own slots in place to signed masks (+BIG fg / -BIG bg).
        s[(0 * 2 + img) * ARR + y] = (v.x > 0.5f) ? BIGF : -BIGF;
        s[(1 * 2 + img) * ARR + y] = (v.y > 0.5f) ? BIGF : -BIGF;
        s[(2 * 2 + img) * ARR + y] = (v.z > 0.5f) ? BIGF : -BIGF;
        s[(3 * 2 + img) * ARR + y] = (v.w > 0.5f) ? BIGF : -BIGF;
        __syncthreads();

        // Thread group q = img scans arrays 4q..4q+3 at site y.
        float mF[4], mN[4];
        scan4s(s + (4 * img) * ARR, y, mF, mN);

        // Pack: V = mF - mN (one is exactly 0); BIG -> +/-inf in fp16.
        #pragma unroll
        for (int j = 0; j < 4; ++j) {
            int a = 4 * img + j;
            int u = a >> 1, m = a & 1;   // column u, image m
            g_V[(m * 4 + b) * IMG + (x0 + u) * HW + y] =
                __float2half(mF[j] - mN[j]);
        }
    }

    // ===================== Grid barrier ==================================
    __threadfence();                 // publish g_V / g_E / g_fgany
    __syncthreads();
    if (tid == 0) {
        atomicAdd((unsigned int*)&g_bar, 1u);
        while (g_bar < NBLK) __nanosleep(32);
    }
    __syncthreads();
    __threadfence();                 // acquire other blocks' writes

    // ===================== Phase 2: horizontal pass + loss ===============
    {
        int yt  = bid & 31;
        int b   = (bid >> 5) & 3;
        int in  = bid >> 7;
        int y0  = yt * 8;

        const __half* V = g_V + (in * 4 + b) * IMG;   // [x][y] layout
        #pragma unroll
        for (int it = 0; it < 4; ++it) {
            int idx = it * 512 + tid;
            int x = idx >> 3;        // x
            int r = idx & 7;         // row within tile
            s[r * ARR + x] = __half2float(V[x * HW + y0 + r]);
        }
        __syncthreads();

        int q = tid >> 8;            // rows 4q..4q+3
        int x = tid & 255;
        float mF[4], mN[4];
        scan4s(s + (4 * q) * ARR, x, mF, mN);

        int fg = g_fgany[in * 4 + b];
        // fp32 tree: pairwise within the 4 terms.
        float t0, t1, t2, t3;
        {
            float dv0 = fminf(mF[0], BIGF) + fminf(mN[0], BIGF);
            float dv1 = fminf(mF[1], BIGF) + fminf(mN[1], BIGF);
            float dv2 = fminf(mF[2], BIGF) + fminf(mN[2], BIGF);
            float dv3 = fminf(mF[3], BIGF) + fminf(mN[3], BIGF);
            const unsigned short* E = g_E + b * IMG + (y0 + 4 * q) * HW + x;
            t0 = (float)E[0 * HW] * (1.0f / 65535.0f) * dv0;
            t1 = (float)E[1 * HW] * (1.0f / 65535.0f) * dv1;
            t2 = (float)E[2 * HW] * (1.0f / 65535.0f) * dv2;
            t3 = (float)E[3 * HW] * (1.0f / 65535.0f) * dv3;
        }
        float acc = (t0 + t1) + (t2 + t3);
        if (!fg) acc = 0.0f;         // empty-foreground image contributes 0

        // Warp tree reduce (fp32), then 16 warp sums via reused smem.
        #pragma unroll
        for (int o = 16; o > 0; o >>= 1)
            acc += __shfl_down_sync(0xFFFFFFFFu, acc, o);

        __syncthreads();             // done reading s
        float* ws = s;
        int wid = tid >> 5, lane = tid & 31;
        if (lane == 0) ws[wid] = acc;
        __syncthreads();

        if (wid == 0 && lane == 0) {
            float s0 = 0.f, s1 = 0.f, s2 = 0.f, s3 = 0.f;   // 4-way tree
            #pragma unroll
            for (int w = 0; w < 16; w += 4) {
                s0 += ws[w]; s1 += ws[w + 1]; s2 += ws[w + 2]; s3 += ws[w + 3];
            }
            atomicAdd(&g_accum, (s0 + s1) + (s2 + s3));
            __threadfence();
            unsigned done = atomicAdd(&g_counter, 1u);
            if (done == NBLK - 1) {
                float tot = atomicAdd(&g_accum, 0.0f);      // coherent read
                out[0] = tot * (1.0f / (float)TOTAL);
                // Self-reset device state for the next graph replay.
                g_accum = 0.0f;
                g_counter = 0u;
                g_bar = 0u;
                #pragma unroll
                for (int i2 = 0; i2 < 8; ++i2) g_fgany[i2] = 0;
            }
        }
    }
}

extern "C" void kernel_launch(void* const* d_in, const int* in_sizes, int n_in,
                              void* d_out, int out_size) {
    const float* pred   = (const float*)d_in[0];
    const float* target = (const float*)d_in[1];
    float* out = (float*)d_out;

    fused_kernel<<<NBLK, 512>>>(pred, target, out);
}

// round 9
// speedup vs baseline: 1.4706x; 1.4706x over previous
#include <cuda_runtime.h>
#include <cuda_fp16.h>

// HausdorffDTLoss, [4,1,256,256] fp32. Single fused kernel, all-fp32.
// loss = mean( (pred-target)^2 * (pred_dt^2 + target_dt^2) ),
// dt^2(pixel) = squared distance to nearest opposite-class pixel
//   (= edt(fg)^2 + edt(~fg)^2, exactly one term nonzero; BIG-clamped).
// Pass 1 (vertical): binary input -> nearest-opposite-bit search on packed
//   column bitmasks (ballot + ffs/clz). Signed fp16 distance g (+fg/-bg),
//   +/-inf when the column has no opposite pixel.
// Pass 2 (horizontal): windowed min-plus with per-lane early exit over the
//   OWN field only: at every site the other field is identically 0 in both
//   passes (its input is 0 there). Candidate decode u = max(s*v, 0):
//   same-class j -> g_j, opposite-class j -> 0 (both exact).
// Exactness: every candidate is g_j^2 + d^2 evaluated in fp32 on exact
// integers; d^2 >= m can't win; clamped-index re-evaluations are dominated.

#define BIGF 1e10f
#define HW 256
#define IMG 65536
#define TOTAL 262144
#define ARR 257
#define NBLK 256

// [img(2)][b(4)][x][y] signed vertical distance (fp16, y fast; transposed)
__device__ __align__(16) __half g_V[2 * 4 * IMG];
__device__ int g_fgany[8];          // [img*4 + b]; zero-init, self-reset
__device__ float g_accum;           // zero-init, self-reset
__device__ unsigned int g_counter;  // zero-init, self-reset
__device__ volatile unsigned int g_bar;  // zero-init, self-reset

__global__ __launch_bounds__(512, 2) void fused_kernel(
    const float* __restrict__ pred, const float* __restrict__ target,
    float* __restrict__ out)
{
    __shared__ __align__(16) float s[8 * ARR];       // reused across phases
    unsigned int* msk = (unsigned int*)s;            // [8 cols][8 words]
    int bid = blockIdx.x;            // 0..255
    int tid = threadIdx.x;

    // ============ Phase 1: vertical pass via bitmask search ==============
    {
        int xt  = bid & 63;
        int b   = bid >> 6;
        int x0  = xt * 4;
        int img = tid >> 8;          // 0 = pred, 1 = target (warp-uniform)
        int y   = tid & 255;
        int w0  = y >> 5;            // warp-uniform word index
        int lb  = y & 31;            // = lane id

        const float* im = (img ? target : pred) + b * IMG + y * HW + x0;
        float4 v = *reinterpret_cast<const float4*>(im);   // coalesced 16B

        bool c0 = v.x > 0.5f, c1 = v.y > 0.5f, c2 = v.z > 0.5f, c3 = v.w > 0.5f;
        unsigned b0 = __ballot_sync(~0u, c0);
        unsigned b1 = __ballot_sync(~0u, c1);
        unsigned b2 = __ballot_sync(~0u, c2);
        unsigned b3 = __ballot_sync(~0u, c3);
        if (lb == 0) {               // lane 0 publishes this warp's words
            msk[(img * 4 + 0) * 8 + w0] = b0;
            msk[(img * 4 + 1) * 8 + w0] = b1;
            msk[(img * 4 + 2) * 8 + w0] = b2;
            msk[(img * 4 + 3) * 8 + w0] = b3;
        }
        __syncthreads();

        // fg_any: one thread per image ORs its 32 mask words (1 atomic/img).
        if ((tid & 255) == 0) {
            const uint4* mw = (const uint4*)(msk + img * 32);
            unsigned o = 0;
            #pragma unroll
            for (int k = 0; k < 8; ++k) {
                uint4 m4 = mw[k];
                o |= m4.x | m4.y | m4.z | m4.w;
            }
            if (o) atomicOr(&g_fgany[img * 4 + b], 1);
        }

        bool cls[4] = {c0, c1, c2, c3};
        #pragma unroll
        for (int k = 0; k < 4; ++k) {
            const unsigned* M = msk + (img * 4 + k) * 8;
            unsigned inv = cls[k] ? 0xFFFFFFFFu : 0u;
            unsigned T0 = M[w0] ^ inv;       // 1-bits = opposite class

            int dup = 1 << 20;               // search up (y+1..255)
            unsigned rem = T0 & (0xFFFFFFFEu << lb);
            if (rem) dup = __ffs(rem) - 1 - lb;
            else {
                #pragma unroll 1
                for (int w = w0 + 1; w < 8; ++w) {
                    unsigned tw = M[w] ^ inv;
                    if (tw) { dup = ((w - w0) << 5) + __ffs(tw) - 1 - lb; break; }
                }
            }
            int ddn = 1 << 20;               // search down (y-1..0)
            rem = T0 & ((1u << lb) - 1u);
            if (rem) ddn = lb + __clz(rem) - 31;
            else {
                #pragma unroll 1
                for (int w = w0 - 1; w >= 0; --w) {
                    unsigned tw = M[w] ^ inv;
                    if (tw) { ddn = ((w0 - w) << 5) + lb + __clz(tw) - 31; break; }
                }
            }
            int g = min(dup, ddn);           // >= 1
            float gf = (g > 256) ? BIGF : (float)g;   // BIGF -> fp16 inf
            g_V[(img * 4 + b) * IMG + (x0 + k) * HW + y] =
                __float2half(cls[k] ? gf : -gf);
        }
    }

    // ===================== Grid barrier ==================================
    __threadfence();                 // publish g_V / g_fgany
    __syncthreads();
    if (tid == 0) {
        atomicAdd((unsigned int*)&g_bar, 1u);
        while (g_bar < NBLK) __nanosleep(32);
    }
    __syncthreads();
    __threadfence();                 // acquire other blocks' writes

    // ============ Phase 2: horizontal pass + loss ========================
    {
        int yt = bid & 31;
        int b  = (bid >> 5) & 3;
        int in = bid >> 7;
        int y0 = yt * 8;

        const __half* V = g_V + (in * 4 + b) * IMG;   // [x][y] layout
        #pragma unroll
        for (int it = 0; it < 4; ++it) {
            int idx = it * 512 + tid;
            int x = idx >> 3;        // x
            int r = idx & 7;         // row within tile
            s[r * ARR + x] = __half2float(V[x * HW + y0 + r]);
        }
        __syncthreads();

        int q = tid >> 8;            // rows 4q..4q+3
        int x = tid & 255;
        const float* A = s + (4 * q) * ARR;

        float m[4], sg[4];
        #pragma unroll
        for (int j = 0; j < 4; ++j) {
            float vo = A[x + j * ARR];
            float sj = vo >= 0.0f ? 1.0f : -1.0f;   // own class sign
            sg[j] = sj;
            float u = sj * vo;                      // = g (or +inf)
            m[j] = u * u;                           // own candidate g^2
        }
        float d2 = 1.0f, st = 3.0f;  // d2 = d*d, st = 2d+1 (exact fp32)
        #pragma unroll 1
        for (int d = 1; d < 256; ++d) {
            float mx = fmaxf(fmaxf(m[0], m[1]), fmaxf(m[2], m[3]));
            if (d2 >= mx) break;     // no farther candidate can win any min
            int il = x - d; il = il < 0 ? 0 : il;   // clamped: dominated
            int ir = x + d; ir = ir > 255 ? 255 : ir;
            #pragma unroll
            for (int j = 0; j < 4; ++j) {
                float ul = fmaxf(sg[j] * A[il + j * ARR], 0.0f);
                float ur = fmaxf(sg[j] * A[ir + j * ARR], 0.0f);
                float u = fminf(ul, ur);
                m[j] = fminf(m[j], __fmaf_rn(u, u, d2));
            }
            d2 += st; st += 2.0f;
        }

        int fg = g_fgany[in * 4 + b];
        const float* pr = pred + b * IMG;
        const float* tg = target + b * IMG;
        float t[4];
        #pragma unroll
        for (int j = 0; j < 4; ++j) {
            float dv = fminf(m[j], BIGF);           // BIG clamp (inf -> BIG)
            int ii = (y0 + 4 * q + j) * HW + x;
            float e = pr[ii] - tg[ii];
            t[j] = e * e * dv;
        }
        float acc = (t[0] + t[1]) + (t[2] + t[3]);
        if (!fg) acc = 0.0f;         // empty-foreground image contributes 0

        // Warp tree reduce, then 16 warp sums via reused smem.
        #pragma unroll
        for (int o = 16; o > 0; o >>= 1)
            acc += __shfl_down_sync(0xFFFFFFFFu, acc, o);

        __syncthreads();             // scans/loss done reading s
        float* ws = s;
        int wid = tid >> 5, lane = tid & 31;
        if (lane == 0) ws[wid] = acc;
        __syncthreads();

        if (tid == 0) {
            float s0 = 0.f, s1 = 0.f, s2 = 0.f, s3 = 0.f;   // 4-way tree
            #pragma unroll
            for (int w = 0; w < 16; w += 4) {
                s0 += ws[w]; s1 += ws[w + 1]; s2 += ws[w + 2]; s3 += ws[w + 3];
            }
            atomicAdd(&g_accum, (s0 + s1) + (s2 + s3));
            __threadfence();
            unsigned done = atomicAdd(&g_counter, 1u);
            if (done == NBLK - 1) {
                float tot = atomicAdd(&g_accum, 0.0f);      // coherent read
                out[0] = tot * (1.0f / (float)TOTAL);
                // Self-reset device state for the next graph replay.
                g_accum = 0.0f;
                g_counter = 0u;
                g_bar = 0u;
                #pragma unroll
                for (int i2 = 0; i2 < 8; ++i2) g_fgany[i2] = 0;
            }
        }
    }
}

extern "C" void kernel_launch(void* const* d_in, const int* in_sizes, int n_in,
                              void* d_out, int out_size) {
    const float* pred   = (const float*)d_in[0];
    const float* target = (const float*)d_in[1];
    float* out = (float*)d_out;

    fused_kernel<<<NBLK, 512>>>(pred, target, out);
}

// round 10
// speedup vs baseline: 1.5464x; 1.0515x over previous
#include <cuda_runtime.h>
#include <cuda_fp16.h>

// HausdorffDTLoss, [4,1,256,256] fp32. Two kernels, all-fp32.
// loss = mean( (pred-target)^2 * (pred_dt^2 + target_dt^2) ),
// dt^2(pixel) = squared distance to nearest opposite-class pixel
//   (= edt(fg)^2 + edt(~fg)^2 with exactly one term nonzero; BIG-clamped).
// Stage 1 (vertical): binary input -> nearest-opposite-bit search on packed
//   column bitmasks (ballot + ffs/clz). Signed fp16 distance (+fg/-bg),
//   +/-inf when the column has no opposite pixel. 2 searches/thread.
// Stage 2 (horizontal): windowed min-plus over the OWN field only (the
//   other field is identically 0 at every site in both passes). Candidates
//   pre-decoded at tile load into Ufg/Ubg arrays; per-site pointer select.
//   2 arrays/thread, per-lane early exit.
// Exactness: every candidate is g_j^2 + d^2 in fp32 on exact integers;
// d^2 >= m can't win; clamped-index re-evaluations are dominated.

#define BIGF 1e10f
#define HW 256
#define IMG 65536
#define TOTAL 262144
#define RS 584      // smem row stride, floats (RS % 32 == 8 -> store banks ok)
#define AO 288      // Ubg offset within row (AO % 32 == 0 -> scan banks ok)
#define NBLK2 512

// [img(2)][b(4)][x][y] signed vertical distance (fp16, y fast; transposed)
__device__ __align__(16) __half g_V[2 * 4 * IMG];
__device__ int g_fgany[8];          // [img*4 + b]; zero-init, self-reset
__device__ float g_accum;           // zero-init, self-reset
__device__ unsigned int g_counter;  // zero-init, self-reset

// ---------------------------------------------------------------------------
// Stage 1: 1024 blocks x 256 threads. Block = (img, b, 2-column tile).
// Thread y: load float2, ballot 2 column masks, 2 nearest-bit searches.
// ---------------------------------------------------------------------------
__global__ __launch_bounds__(256) void stage1_kernel(
    const float* __restrict__ pred, const float* __restrict__ target)
{
    __shared__ unsigned msk[2][8];
    __shared__ unsigned sany[8];

    int bid = blockIdx.x;            // 0..1023
    int xt  = bid & 127;
    int b   = (bid >> 7) & 3;
    int img = bid >> 9;
    int x0  = xt * 2;
    int y   = threadIdx.x;
    int w0  = y >> 5, lb = y & 31;

    const float* im = (img ? target : pred) + b * IMG + y * HW + x0;
    float2 v = *reinterpret_cast<const float2*>(im);     // 8B x 32 = 256B
    bool c0 = v.x > 0.5f, c1 = v.y > 0.5f;
    unsigned b0 = __ballot_sync(~0u, c0);
    unsigned b1 = __ballot_sync(~0u, c1);
    if (lb == 0) { msk[0][w0] = b0; msk[1][w0] = b1; sany[w0] = b0 | b1; }
    __syncthreads();

    if (y == 0) {                    // one fire-and-forget RED per block
        unsigned o = 0;
        #pragma unroll
        for (int k = 0; k < 8; ++k) o |= sany[k];
        if (o) atomicOr(&g_fgany[img * 4 + b], 1);
    }

    bool cls[2] = {c0, c1};
    #pragma unroll
    for (int k = 0; k < 2; ++k) {
        const unsigned* M = msk[k];
        unsigned inv = cls[k] ? 0xFFFFFFFFu : 0u;
        unsigned T0 = M[w0] ^ inv;   // 1-bits = opposite class

        int dup = 1 << 20;           // search up (y+1..255)
        unsigned rem = T0 & (0xFFFFFFFEu << lb);
        if (rem) dup = __ffs(rem) - 1 - lb;
        else {
            #pragma unroll 1
            for (int w = w0 + 1; w < 8; ++w) {
                unsigned tw = M[w] ^ inv;
                if (tw) { dup = ((w - w0) << 5) + __ffs(tw) - 1 - lb; break; }
            }
        }
        int ddn = 1 << 20;           // search down (y-1..0)
        rem = T0 & ((1u << lb) - 1u);
        if (rem) ddn = lb + __clz(rem) - 31;
        else {
            #pragma unroll 1
            for (int w = w0 - 1; w >= 0; --w) {
                unsigned tw = M[w] ^ inv;
                if (tw) { ddn = ((w0 - w) << 5) + lb + __clz(tw) - 31; break; }
            }
        }
        int g = min(dup, ddn);       // >= 1
        float gf = (g > 256) ? BIGF : (float)g;   // BIGF -> fp16 inf
        g_V[(img * 4 + b) * IMG + (x0 + k) * HW + y] =
            __float2half(cls[k] ? gf : -gf);      // 2B x 32 y = 64B
    }
}

// ---------------------------------------------------------------------------
// Stage 2: 512 blocks x 512 threads. Block = (img, b, 4-row tile).
// Tile load decodes signed field into Ufg/Ubg rows. Thread (q = tid>>8,
// x = tid&255) scans rows 2q, 2q+1 jointly (ILP-2) with per-lane exit,
// then accumulates the loss; block reduce; last block finalizes + resets.
// ---------------------------------------------------------------------------
__global__ __launch_bounds__(512, 3) void stage2_kernel(
    const float* __restrict__ pred, const float* __restrict__ target,
    float* __restrict__ out)
{
    __shared__ __align__(16) float s[4 * RS];    // 4 rows x (Ufg | Ubg)

    int bid = blockIdx.x;            // 0..511
    int yt  = bid & 63;
    int b   = (bid >> 6) & 3;
    int img = bid >> 8;
    int y0  = yt * 4;
    int tid = threadIdx.x;

    const __half* V = g_V + (img * 4 + b) * IMG;   // [x][y] layout
    #pragma unroll
    for (int it = 0; it < 2; ++it) {
        int idx = it * 512 + tid;
        int x = idx >> 2, r = idx & 3;             // 4 consecutive halfs per x
        float v = __half2float(V[x * HW + y0 + r]);
        s[r * RS + x]      = fmaxf(v, 0.0f);       // Ufg
        s[r * RS + AO + x] = fmaxf(-v, 0.0f);      // Ubg
    }
    __syncthreads();

    int q = tid >> 8;                // rows 2q, 2q+1
    int x = tid & 255;

    const float* R0 = s + (2 * q) * RS;
    const float* R1 = R0 + RS;
    float vf0 = R0[x], vb0 = R0[AO + x];
    float vf1 = R1[x], vb1 = R1[AO + x];
    bool  cA = vf0 > 0.0f;           // own class of site (row 2q)
    bool  cB = vf1 > 0.0f;
    const float* PA = cA ? R0 : (R0 + AO);
    const float* PB = cB ? R1 : (R1 + AO);
    float uA = cA ? vf0 : vb0;  float mA = uA * uA;   // own candidate g^2
    float uB = cB ? vf1 : vb1;  float mB = uB * uB;

    float d2 = 1.0f, st = 3.0f;      // d2 = d*d, st = 2d+1 (exact fp32)
    #pragma unroll 1
    for (int d = 1; d < 256; ++d) {
        if (d2 >= fmaxf(mA, mB)) break;   // no farther candidate can win
        int il = x - d; il = il < 0 ? 0 : il;        // clamped: dominated
        int ir = x + d; ir = ir > 255 ? 255 : ir;
        float ua = fminf(PA[il], PA[ir]);
        mA = fminf(mA, __fmaf_rn(ua, ua, d2));
        float ub = fminf(PB[il], PB[ir]);
        mB = fminf(mB, __fmaf_rn(ub, ub, d2));
        d2 += st; st += 2.0f;
    }

    int fg = g_fgany[img * 4 + b];
    const float* pr = pred + b * IMG;
    const float* tg = target + b * IMG;
    int i0 = (y0 + 2 * q) * HW + x;
    float e0 = pr[i0] - tg[i0];
    float e1 = pr[i0 + HW] - tg[i0 + HW];
    float acc = e0 * e0 * fminf(mA, BIGF) + e1 * e1 * fminf(mB, BIGF);
    if (!fg) acc = 0.0f;             // empty-foreground image contributes 0

    // Warp tree reduce, then 16 warp sums via reused smem.
    #pragma unroll
    for (int o = 16; o > 0; o >>= 1)
        acc += __shfl_down_sync(0xFFFFFFFFu, acc, o);

    __syncthreads();                 // done reading s
    float* ws = s;
    int wid = tid >> 5, lane = tid & 31;
    if (lane == 0) ws[wid] = acc;
    __syncthreads();

    if (tid == 0) {
        float s0 = 0.f, s1 = 0.f, s2 = 0.f, s3 = 0.f;   // 4-way tree
        #pragma unroll
        for (int w = 0; w < 16; w += 4) {
            s0 += ws[w]; s1 += ws[w + 1]; s2 += ws[w + 2]; s3 += ws[w + 3];
        }
        atomicAdd(&g_accum, (s0 + s1) + (s2 + s3));
        __threadfence();
        unsigned done = atomicAdd(&g_counter, 1u);
        if (done == NBLK2 - 1) {
            float tot = atomicAdd(&g_accum, 0.0f);      // coherent read
            out[0] = tot * (1.0f / (float)TOTAL);
            // Self-reset device state for the next graph replay.
            g_accum = 0.0f;
            g_counter = 0u;
            #pragma unroll
            for (int i2 = 0; i2 < 8; ++i2) g_fgany[i2] = 0;
        }
    }
}

extern "C" void kernel_launch(void* const* d_in, const int* in_sizes, int n_in,
                              void* d_out, int out_size) {
    const float* pred   = (const float*)d_in[0];
    const float* target = (const float*)d_in[1];
    float* out = (float*)d_out;

    stage1_kernel<<<1024, 256>>>(pred, target);
    stage2_kernel<<<NBLK2, 512>>>(pred, target, out);
}